// round 10
// baseline (speedup 1.0000x reference)
#include <cuda_runtime.h>
#include <cuda_bf16.h>
#include <math.h>
#include <cstdint>

// ---------------------------------------------------------------------------
// Problem constants
// ---------------------------------------------------------------------------
#define BSZ     4
#define LSEQ    4096
#define DM      1048
#define PD      1048
#define NLAYERS 3
#define MROWS   (BSZ*LSEQ)              // 16384
#define MD      ((size_t)MROWS * DM)
#define KP      1088                    // K padded
#define NCHUNK  (KP/32)                 // 34 (BK=32)
#define NP1     1280                    // 1048 padded to 256 (5 tiles)
#define NP2     2304                    // 2096 padded to 256 (9 tiles)

#define MD_F   17170432ULL
#define ACT_F  8912896ULL
#define W1_F   696320ULL                // (1280*1088 bf16)/2
#define W2_F   1253376ULL               // (2304*1088 bf16)/2
#define WL_F   (10ULL*W1_F + 2ULL*W2_F)

#define OFF_H    0ULL
#define OFF_GRE  (1ULL*MD_F)
#define OFF_GIM  (2ULL*MD_F)
#define OFF_Y    (3ULL*MD_F)
#define OFF_Z    (4ULL*MD_F)
#define OFF_H2   (5ULL*MD_F)
#define OFF_ACT  (7ULL*MD_F)
#define OFF_WB   (OFF_ACT + 10ULL*ACT_F)
#define OFF_POOL (OFF_WB + 3ULL*WL_F)
#define TOT_F    (OFF_POOL + 8192ULL)

__device__ __align__(1024) float g_scratch[TOT_F];

#if defined(__CUDA_ARCH_FEAT_SM103_ALL) || defined(__CUDA_ARCH_SPECIFIC__) || defined(__CUDA_ARCH_FEAT_SM100_ALL)
#define HAS_TCGEN05 1
#else
#define HAS_TCGEN05 0
#endif

__device__ __forceinline__ float gelu_exact(float x) {
    return 0.5f * x * (1.0f + erff(x * 0.70710678118654752f));
}

__device__ __forceinline__ uint32_t smem_u32_of(const void* p) {
    uint32_t a;
    asm("{ .reg .u64 t; cvta.to.shared.u64 t, %1; cvt.u32.u64 %0, t; }"
        : "=r"(a) : "l"(p));
    return a;
}

__device__ __forceinline__ void split_bf16(float v, __nv_bfloat16& h, __nv_bfloat16& l) {
    h = __float2bfloat16(v);
    l = __float2bfloat16(v - __bfloat162float(h));
}

__device__ __forceinline__ uint32_t elect_one_pred() {
    uint32_t pred;
    asm volatile(
        "{\n\t.reg .pred p;\n\telect.sync _|p, 0xFFFFFFFF;\n\t"
        "selp.b32 %0, 1, 0, p;\n\t}" : "=r"(pred));
    return pred;
}

// ---------------------------------------------------------------------------
// Shared PTX macros
// ---------------------------------------------------------------------------
#define CP_ASYNC_16(saddr, gptr) \
    asm volatile("cp.async.cg.shared.global [%0], [%1], 16;" \
        :: "r"(saddr), "l"(gptr) : "memory")
#define CP_ASYNC_MBAR_ARRIVE_NOINC(mbar) \
    asm volatile("cp.async.mbarrier.arrive.noinc.shared::cta.b64 [%0];" \
        :: "r"((uint32_t)(mbar)) : "memory")

#define MBARRIER_INIT(mbar, count) \
    asm volatile("mbarrier.init.shared.b64 [%0], %1;" \
        :: "r"((uint32_t)(mbar)), "r"((uint32_t)(count)) : "memory")
#define MBARRIER_WAIT_PARITY(mbar, parity) do { \
    uint32_t _mbar = (uint32_t)(mbar); \
    uint32_t _parity = (uint32_t)(parity); \
    uint32_t _done; \
    asm volatile( \
        "{\n\t.reg .pred p;\n\t" \
        "mbarrier.try_wait.parity.acquire.cta.shared::cta.b64 p, [%1], %2;\n\t" \
        "selp.b32 %0, 1, 0, p;\n\t}" \
        : "=r"(_done) : "r"(_mbar), "r"(_parity) : "memory"); \
    if (!_done) { \
        asm volatile( \
            "{\n\t.reg .pred P1;\n\t" \
            "WAIT_LOOP_%=:\n\t" \
            "mbarrier.try_wait.parity.acquire.cta.shared::cta.b64 P1, [%0], %1, 0x989680;\n\t" \
            "@P1 bra.uni WAIT_DONE_%=;\n\t" \
            "bra.uni WAIT_LOOP_%=;\n\t" \
            "WAIT_DONE_%=:\n\t}" \
            :: "r"(_mbar), "r"(_parity) : "memory"); \
    } \
} while(0)

// stage = 4 planes x (256 rows x 64B) = 64KB; 3 stages + 1KB ctrl
#define TPLANE 16384
#define TSTAGE 65536
#define GEMM_SMEM_BYTES (1024 + 3*TSTAGE)   // 197632

#if HAS_TCGEN05
// ===== tcgen05 path: 256x256 tile, BK=32, SW64, decoupled mbarrier pipeline ==
#define TCGEN05_ALLOC(saddr, nCols) \
    asm volatile("tcgen05.alloc.cta_group::1.sync.aligned.shared::cta.b32 [%0], %1;" \
        :: "r"((uint32_t)(saddr)), "r"((uint32_t)(nCols)) : "memory")
#define TCGEN05_DEALLOC(tmem, nCols) \
    asm volatile("tcgen05.dealloc.cta_group::1.sync.aligned.b32 %0, %1;" \
        :: "r"(tmem), "r"((uint32_t)(nCols)))
#define TCGEN05_RELINQUISH() \
    asm volatile("tcgen05.relinquish_alloc_permit.cta_group::1.sync.aligned;")
#define TCGEN05_COMMIT(mbar) \
    asm volatile("tcgen05.commit.cta_group::1.mbarrier::arrive::one.shared::cluster.b64 [%0];" \
        :: "r"((uint32_t)(mbar)) : "memory")
#define TCGEN05_FENCE_AFTER() \
    asm volatile("tcgen05.fence::after_thread_sync;" ::: "memory")
#define TCGEN05_WAIT_LD() \
    asm volatile("tcgen05.wait::ld.sync.aligned;" ::: "memory")
#define FENCE_PROXY_ASYNC() \
    asm volatile("fence.proxy.async.shared::cta;" ::: "memory")
#define TCGEN05_LD_32X32B_X32(r, taddr) \
    asm volatile( \
        "tcgen05.ld.sync.aligned.32x32b.x32.b32 " \
        "{%0, %1, %2, %3, %4, %5, %6, %7, " \
        " %8, %9, %10, %11, %12, %13, %14, %15, " \
        " %16, %17, %18, %19, %20, %21, %22, %23, " \
        " %24, %25, %26, %27, %28, %29, %30, %31}, [%32];" \
        : "=r"((r)[0]),  "=r"((r)[1]),  "=r"((r)[2]),  "=r"((r)[3]), \
          "=r"((r)[4]),  "=r"((r)[5]),  "=r"((r)[6]),  "=r"((r)[7]), \
          "=r"((r)[8]),  "=r"((r)[9]),  "=r"((r)[10]), "=r"((r)[11]), \
          "=r"((r)[12]), "=r"((r)[13]), "=r"((r)[14]), "=r"((r)[15]), \
          "=r"((r)[16]), "=r"((r)[17]), "=r"((r)[18]), "=r"((r)[19]), \
          "=r"((r)[20]), "=r"((r)[21]), "=r"((r)[22]), "=r"((r)[23]), \
          "=r"((r)[24]), "=r"((r)[25]), "=r"((r)[26]), "=r"((r)[27]), \
          "=r"((r)[28]), "=r"((r)[29]), "=r"((r)[30]), "=r"((r)[31]) \
        : "r"(taddr))

// SW64 K-major: layout=4, version=1, SBO=32 (512B = 8 rows x 64B), LBO=1
static constexpr uint64_t SMEM_DESC_BASE_SW64 =
    (uint64_t(4) << 61) | (uint64_t(1) << 46) | (uint64_t(32) << 32) | (uint64_t(1) << 16);
#define MAKE_SMEM_DESC64(base_addr) \
    (SMEM_DESC_BASE_SW64 | ((uint64_t)((base_addr) >> 4) & 0x3FFF))

// idesc: kind::f16, dtype=F32, atype=btype=BF16, M=128, N=256
static constexpr uint32_t GIDESC =
    (1u<<4) | (1u<<7) | (1u<<10) | ((256u/8u)<<17) | ((128u/16u)<<24);

__device__ __forceinline__ void mma_f16_ss(uint32_t d_tmem, uint64_t a_desc,
                                           uint64_t b_desc, uint32_t en) {
    asm volatile(
        "{\n\t.reg .pred p;\n\tsetp.ne.u32 p, %4, 0;\n\t"
        "tcgen05.mma.cta_group::1.kind::f16 [%0], %1, %2, %3, {%5, %5, %5, %5}, p;\n\t}"
        :: "r"(d_tmem), "l"(a_desc), "l"(b_desc), "r"(GIDESC), "r"(en), "r"(0u)
        : "memory");
}

// smem: [0] tmem ptr, [16..40) full[3], [40..64) done[3], data at 1024
__global__ __launch_bounds__(256) void gemm_bf16x3(
    const __nv_bfloat16* __restrict__ Ah, const __nv_bfloat16* __restrict__ Al,
    const __nv_bfloat16* __restrict__ Bh, const __nv_bfloat16* __restrict__ Bl,
    float* __restrict__ C, int N, float alpha, float beta)
{
    extern __shared__ __align__(1024) char smem[];
    const uint32_t sbase = smem_u32_of(smem);
    const int tid = threadIdx.x;
    const int wid = tid >> 5;
    const int lid = tid & 31;

    if (wid == 0) {
        TCGEN05_ALLOC(sbase + 0, 512);
        TCGEN05_RELINQUISH();
    }
    if (tid == 0) {
        #pragma unroll
        for (int s = 0; s < 3; s++) {
            MBARRIER_INIT(sbase + 16 + 8 * s, 256);  // full[s]
            MBARRIER_INIT(sbase + 40 + 8 * s, 1);    // done[s]
        }
    }
    __syncthreads();
    uint32_t tmem;
    asm volatile("ld.shared.b32 %0, [%1];" : "=r"(tmem) : "r"(sbase));

    const __nv_bfloat16* srcs[4];
    srcs[0] = Ah + (size_t)blockIdx.y * 256 * KP;
    srcs[1] = Al + (size_t)blockIdx.y * 256 * KP;
    srcs[2] = Bh + (size_t)blockIdx.x * 256 * KP;
    srcs[3] = Bl + (size_t)blockIdx.x * 256 * KP;

    // 4 planes x 256 rows x 4 x 16B = 4096 units; 16 per thread.
    // SW64 swizzle at 16B units: j (0..3) -> j ^ ((r>>1)&3).
    auto prefetch = [&](int kc) {
        const int s = kc % 3;
        const int k0 = kc * 32;
        const uint32_t stb = sbase + 1024 + s * TSTAGE;
        #pragma unroll
        for (int i = 0; i < 16; i++) {
            int c  = i * 256 + tid;
            int pl = c >> 10;
            int r  = (c >> 2) & 255;
            int j  = c & 3;
            uint32_t dst = stb + pl * TPLANE + r * 64 + ((j ^ ((r >> 1) & 3)) << 4);
            CP_ASYNC_16(dst, srcs[pl] + (size_t)r * KP + k0 + j * 8);
        }
        CP_ASYNC_MBAR_ARRIVE_NOINC(sbase + 16 + 8 * s);
    };

    const uint32_t ismma = (wid == 0) ? elect_one_pred() : 0u;

    prefetch(0);
    prefetch(1);
    prefetch(2);

    for (int kc = 0; kc < NCHUNK; kc++) {
        const int s = kc % 3;
        const uint32_t ph = (kc / 3) & 1;

        if (ismma) {
            MBARRIER_WAIT_PARITY(sbase + 16 + 8 * s, ph);
            FENCE_PROXY_ASYNC();
            const uint32_t stb = sbase + 1024 + s * TSTAGE;
            uint64_t dA0h = MAKE_SMEM_DESC64(stb);
            uint64_t dA1h = MAKE_SMEM_DESC64(stb + 8192);           // rows 128..255
            uint64_t dA0l = MAKE_SMEM_DESC64(stb + TPLANE);
            uint64_t dA1l = MAKE_SMEM_DESC64(stb + TPLANE + 8192);
            uint64_t dBh  = MAKE_SMEM_DESC64(stb + 2 * TPLANE);
            uint64_t dBl  = MAKE_SMEM_DESC64(stb + 3 * TPLANE);
            #pragma unroll
            for (int ks = 0; ks < 2; ks++) {
                uint32_t en = (kc != 0) || (ks != 0);
                mma_f16_ss(tmem +   0, dA0h + ks * 2, dBh + ks * 2, en);
                mma_f16_ss(tmem + 256, dA1h + ks * 2, dBh + ks * 2, en);
                mma_f16_ss(tmem +   0, dA0h + ks * 2, dBl + ks * 2, 1u);
                mma_f16_ss(tmem + 256, dA1h + ks * 2, dBl + ks * 2, 1u);
                mma_f16_ss(tmem +   0, dA0l + ks * 2, dBh + ks * 2, 1u);
                mma_f16_ss(tmem + 256, dA1l + ks * 2, dBh + ks * 2, 1u);
            }
            TCGEN05_COMMIT(sbase + 40 + 8 * s);
        }

        if (kc + 3 < NCHUNK) {
            MBARRIER_WAIT_PARITY(sbase + 40 + 8 * s, ph);
            prefetch(kc + 3);
        }
    }

    if (ismma) {
        int pc = NCHUNK - 1;
        MBARRIER_WAIT_PARITY(sbase + 40 + 8 * (pc % 3), (pc / 3) & 1);
    }
    __syncthreads();
    TCGEN05_FENCE_AFTER();

    // epilogue: warps 0-3 read TMEM; two M-halves x 8 col-blocks
    if (wid < 4) {
        const int nbase = blockIdx.x * 256;
        #pragma unroll
        for (int h = 0; h < 2; h++) {
            const size_t m = (size_t)blockIdx.y * 256 + h * 128 + wid * 32 + lid;
            float* crow = C + m * (size_t)N;
            for (int cb = 0; cb < 8; cb++) {
                uint32_t r[32];
                TCGEN05_LD_32X32B_X32(r, tmem + h * 256 + cb * 32);
                TCGEN05_WAIT_LD();
                #pragma unroll
                for (int c = 0; c < 32; c += 4) {
                    int n = nbase + cb * 32 + c;
                    if (n + 3 < N) {
                        float4 v;
                        v.x = alpha * __uint_as_float(r[c + 0]);
                        v.y = alpha * __uint_as_float(r[c + 1]);
                        v.z = alpha * __uint_as_float(r[c + 2]);
                        v.w = alpha * __uint_as_float(r[c + 3]);
                        if (beta != 0.f) {
                            float4 o = *reinterpret_cast<const float4*>(crow + n);
                            v.x = fmaf(beta, o.x, v.x);
                            v.y = fmaf(beta, o.y, v.y);
                            v.z = fmaf(beta, o.z, v.z);
                            v.w = fmaf(beta, o.w, v.w);
                        }
                        *reinterpret_cast<float4*>(crow + n) = v;
                    } else {
                        for (int q = 0; q < 4; q++) {
                            int nn = n + q;
                            if (nn < N) {
                                float v = alpha * __uint_as_float(r[c + q]);
                                if (beta != 0.f) v = fmaf(beta, crow[nn], v);
                                crow[nn] = v;
                            }
                        }
                    }
                }
            }
        }
    }
    __syncthreads();
    if (wid == 0) TCGEN05_DEALLOC(tmem, 512);
}

#else
// ===== naive fallback (generic compile pass only; never executes) ===========
__global__ __launch_bounds__(256) void gemm_bf16x3(
    const __nv_bfloat16* __restrict__ Ah, const __nv_bfloat16* __restrict__ Al,
    const __nv_bfloat16* __restrict__ Bh, const __nv_bfloat16* __restrict__ Bl,
    float* __restrict__ C, int N, float alpha, float beta)
{
    const int tid = threadIdx.x;
    const size_t m = (size_t)blockIdx.y * 256 + tid;
    const int n0 = blockIdx.x * 256;
    const __nv_bfloat16* arh = Ah + m * KP;
    const __nv_bfloat16* arl = Al + m * KP;
    for (int j = 0; j < 256; j++) {
        int n = n0 + j;
        if (n >= N) break;
        const __nv_bfloat16* brh = Bh + (size_t)n * KP;
        const __nv_bfloat16* brl = Bl + (size_t)n * KP;
        float acc = 0.f;
        for (int k = 0; k < KP; k++) {
            float a = __bfloat162float(arh[k]) + __bfloat162float(arl[k]);
            float b = __bfloat162float(brh[k]) + __bfloat162float(brl[k]);
            acc = fmaf(a, b, acc);
        }
        size_t idx = m * (size_t)N + n;
        float v = alpha * acc;
        if (beta != 0.f) v = fmaf(beta, C[idx], v);
        C[idx] = v;
    }
}
#endif

// ---------------------------------------------------------------------------
// Elementwise / row kernels
// ---------------------------------------------------------------------------
__global__ void enc_kernel(const float* __restrict__ x,
                           const float* __restrict__ ew,
                           const float* __restrict__ eb,
                           float* __restrict__ H)
{
    size_t i = (size_t)blockIdx.x * blockDim.x + threadIdx.x;
    if (i >= MD) return;
    int d = (int)(i % DM);
    int m = (int)(i / DM);
    H[i] = fmaf(x[m], ew[d], eb[d]);
}

__global__ __launch_bounds__(256) void ln2_kernel(
    const float* __restrict__ X,
    __nv_bfloat16* __restrict__ Oh, __nv_bfloat16* __restrict__ Ol,
    const float* __restrict__ w1, const float* __restrict__ b1,
    const float* __restrict__ w2, const float* __restrict__ b2)
{
    const int row = blockIdx.x;
    const int tid = threadIdx.x;
    const float* x = X + (size_t)row * DM;
    const size_t ro = (size_t)row * KP;
    __shared__ float sA[256], sB[256];

    float v[5];
    float s = 0.f, ss = 0.f;
    #pragma unroll
    for (int k = 0; k < 5; k++) {
        int d = tid + k * 256;
        float t = (d < DM) ? x[d] : 0.f;
        v[k] = t; s += t; ss += t * t;
    }
    sA[tid] = s; sB[tid] = ss; __syncthreads();
    for (int st = 128; st > 0; st >>= 1) {
        if (tid < st) { sA[tid] += sA[tid + st]; sB[tid] += sB[tid + st]; }
        __syncthreads();
    }
    float mu  = sA[0] * (1.0f / DM);
    float var = sB[0] * (1.0f / DM) - mu * mu;
    float rs  = rsqrtf(var + 1e-5f);
    __syncthreads();

    s = 0.f; ss = 0.f;
    #pragma unroll
    for (int k = 0; k < 5; k++) {
        int d = tid + k * 256;
        float r = 0.f;
        if (d < DM) r = fmaf((v[k] - mu) * rs, w1[d], b1[d]);
        v[k] = r; s += r; ss += r * r;
    }
    sA[tid] = s; sB[tid] = ss; __syncthreads();
    for (int st = 128; st > 0; st >>= 1) {
        if (tid < st) { sA[tid] += sA[tid + st]; sB[tid] += sB[tid + st]; }
        __syncthreads();
    }
    float mu2  = sA[0] * (1.0f / DM);
    float var2 = sB[0] * (1.0f / DM) - mu2 * mu2;
    float rs2  = rsqrtf(var2 + 1e-5f);
    #pragma unroll
    for (int k = 0; k < 5; k++) {
        int d = tid + k * 256;
        if (d < DM) {
            float r2 = fmaf((v[k] - mu2) * rs2, w2[d], b2[d]);
            __nv_bfloat16 h, l; split_bf16(r2, h, l);
            Oh[ro + d] = h; Ol[ro + d] = l;
        } else if (d < KP) {
            Oh[ro + d] = __float2bfloat16(0.f);
            Ol[ro + d] = __float2bfloat16(0.f);
        }
    }
}

__global__ __launch_bounds__(256) void postln_kernel(
    const float* __restrict__ Y,
    const __nv_bfloat16* __restrict__ FXh, const __nv_bfloat16* __restrict__ FXl,
    const float* __restrict__ dv,
    const float* __restrict__ w, const float* __restrict__ b,
    __nv_bfloat16* __restrict__ Oh, __nv_bfloat16* __restrict__ Ol)
{
    const int row = blockIdx.x;
    const int tid = threadIdx.x;
    const float* y = Y + (size_t)row * DM;
    const size_t ro = (size_t)row * KP;
    __shared__ float sA[256], sB[256];

    float v[5];
    float s = 0.f, ss = 0.f;
    #pragma unroll
    for (int k = 0; k < 5; k++) {
        int d = tid + k * 256;
        float z = 0.f;
        if (d < DM) {
            float f = __bfloat162float(FXh[ro + d]) + __bfloat162float(FXl[ro + d]);
            float e = fmaf(dv[d], f, y[d]);
            z = gelu_exact(e) + f;
        }
        v[k] = z; s += z; ss += z * z;
    }
    sA[tid] = s; sB[tid] = ss; __syncthreads();
    for (int st = 128; st > 0; st >>= 1) {
        if (tid < st) { sA[tid] += sA[tid + st]; sB[tid] += sB[tid + st]; }
        __syncthreads();
    }
    float mu  = sA[0] * (1.0f / DM);
    float var = sB[0] * (1.0f / DM) - mu * mu;
    float rs  = rsqrtf(var + 1e-5f);
    #pragma unroll
    for (int k = 0; k < 5; k++) {
        int d = tid + k * 256;
        if (d < DM) {
            float r = fmaf((v[k] - mu) * rs, w[d], b[d]);
            __nv_bfloat16 h, l; split_bf16(r, h, l);
            Oh[ro + d] = h; Ol[ro + d] = l;
        } else if (d < KP) {
            Oh[ro + d] = __float2bfloat16(0.f);
            Ol[ro + d] = __float2bfloat16(0.f);
        }
    }
}

__global__ void scan_kernel(
    const float* __restrict__ GRE, const float* __restrict__ GIM,
    __nv_bfloat16* __restrict__ XRh, __nv_bfloat16* __restrict__ XRl,
    __nv_bfloat16* __restrict__ XIh, __nv_bfloat16* __restrict__ XIl,
    const float* __restrict__ lr_, const float* __restrict__ li_,
    const float* __restrict__ ls_)
{
    int t = blockIdx.x * blockDim.x + threadIdx.x;
    if (t >= BSZ * PD) return;
    int b = t / PD, p = t % PD;

    float lr = lr_[p], li = li_[p];
    float st = expf(ls_[p]);
    float er = expf(lr * st);
    float sn, cs; sincosf(li * st, &sn, &cs);
    float ar = er * cs, ai = er * sn;
    float inv = 1.0f / (lr * lr + li * li);
    float nr = ar - 1.0f;
    float cr = (nr * lr + ai * li) * inv;
    float ci = (ai * lr - nr * li) * inv;

    size_t goff = (size_t)b * LSEQ * PD + p;
    const float* gr = GRE + goff;
    const float* gi = GIM + goff;
    size_t ooff = (size_t)b * LSEQ * KP + p;

    float xr = 0.f, xi = 0.f;
    #pragma unroll 4
    for (int l = 0; l < LSEQ; l++) {
        float ur = gr[(size_t)l * PD];
        float ui = gi[(size_t)l * PD];
        float br = fmaf(cr, ur, -ci * ui);
        float bi = fmaf(cr, ui,  ci * ur);
        float nxr = fmaf(ar, xr, fmaf(-ai, xi, br));
        float nxi = fmaf(ar, xi, fmaf( ai, xr, bi));
        xr = nxr; xi = nxi;
        size_t o = ooff + (size_t)l * KP;
        __nv_bfloat16 h, lo;
        split_bf16(xr, h, lo); XRh[o] = h; XRl[o] = lo;
        split_bf16(xi, h, lo); XIh[o] = h; XIl[o] = lo;
    }
}

__global__ void padscan_kernel(__nv_bfloat16* p0, __nv_bfloat16* p1,
                               __nv_bfloat16* p2, __nv_bfloat16* p3)
{
    int i = blockIdx.x * blockDim.x + threadIdx.x;
    const int PADW = KP - DM;
    if (i >= MROWS * PADW) return;
    int r = i / PADW, c = DM + i % PADW;
    size_t idx = (size_t)r * KP + c;
    __nv_bfloat16 z = __float2bfloat16(0.f);
    p0[idx] = z; p1[idx] = z; p2[idx] = z; p3[idx] = z;
}

__global__ void geglu_kernel(const float* __restrict__ H2,
                             __nv_bfloat16* __restrict__ Th,
                             __nv_bfloat16* __restrict__ Tl)
{
    size_t i = (size_t)blockIdx.x * blockDim.x + threadIdx.x;
    if (i >= (size_t)MROWS * KP) return;
    int d = (int)(i % KP);
    size_t m = i / KP;
    if (d < DM) {
        const float* r = H2 + m * (size_t)(2 * DM);
        float v = r[d] * gelu_exact(r[DM + d]);
        __nv_bfloat16 h, l; split_bf16(v, h, l);
        Th[i] = h; Tl[i] = l;
    } else {
        Th[i] = __float2bfloat16(0.f);
        Tl[i] = __float2bfloat16(0.f);
    }
}

__global__ void addres_kernel(float* __restrict__ H, const float* __restrict__ Z,
                              const __nv_bfloat16* __restrict__ FYh,
                              const __nv_bfloat16* __restrict__ FYl)
{
    size_t i = (size_t)blockIdx.x * blockDim.x + threadIdx.x;
    if (i >= MD) return;
    int d = (int)(i % DM);
    size_t m = i / DM;
    size_t j = m * KP + d;
    H[i] += Z[i] + __bfloat162float(FYh[j]) + __bfloat162float(FYl[j]);
}

__global__ void convw_layer_kernel(
    const float* __restrict__ Bre, const float* __restrict__ Bim,
    const float* __restrict__ Cre, const float* __restrict__ Cim,
    const float* __restrict__ Wd,  const float* __restrict__ We,
    __nv_bfloat16* __restrict__ L)
{
    const size_t W1E = (size_t)NP1 * KP;
    const size_t W2E = (size_t)NP2 * KP;
    int w = blockIdx.y;
    const float* src; __nv_bfloat16 *Wh, *Wl; int N; size_t tot;
    switch (w) {
        case 0: src = Bre; Wh = L;          Wl = L + 1*W1E; N = PD;   tot = W1E; break;
        case 1: src = Bim; Wh = L + 2*W1E;  Wl = L + 3*W1E; N = PD;   tot = W1E; break;
        case 2: src = Cre; Wh = L + 4*W1E;  Wl = L + 5*W1E; N = DM;   tot = W1E; break;
        case 3: src = Cim; Wh = L + 6*W1E;  Wl = L + 7*W1E; N = DM;   tot = W1E; break;
        case 4: src = Wd;  Wh = L + 8*W1E;  Wl = L + 9*W1E; N = DM;   tot = W1E; break;
        default:src = We;  Wh = L + 10*W1E; Wl = L + 10*W1E + W2E; N = 2*DM; tot = W2E; break;
    }
    size_t i = (size_t)blockIdx.x * blockDim.x + threadIdx.x;
    if (i >= tot) return;
    int n = (int)(i / KP), k = (int)(i % KP);
    float v = (n < N && k < DM) ? src[(size_t)n * DM + k] : 0.f;
    __nv_bfloat16 h, l; split_bf16(v, h, l);
    Wh[i] = h; Wl[i] = l;
}

__global__ void zero_kernel(float* __restrict__ P, int n)
{
    int i = blockIdx.x * blockDim.x + threadIdx.x;
    if (i < n) P[i] = 0.f;
}

#define POOL_CHUNKS 32
__global__ void pool_kernel(const float* __restrict__ H, float* __restrict__ POOL)
{
    int t = blockIdx.x * blockDim.x + threadIdx.x;
    if (t >= BSZ * DM) return;
    int b = t / DM, d = t % DM;
    const int CL = LSEQ / POOL_CHUNKS;
    int l0 = blockIdx.y * CL;
    const float* h = H + (size_t)b * LSEQ * DM + (size_t)l0 * DM + d;
    float s = 0.f;
    #pragma unroll 8
    for (int l = 0; l < CL; l++) s += h[(size_t)l * DM];
    atomicAdd(&POOL[t], s);
}

__global__ void head_kernel(const float* __restrict__ POOL,
                            const float* __restrict__ hw,
                            const float* __restrict__ hb,
                            float* __restrict__ out)
{
    int b = blockIdx.x;
    int tid = threadIdx.x;
    __shared__ float sA[256];
    float s = 0.f;
    for (int d = tid; d < DM; d += 256) s = fmaf(POOL[b * DM + d], hw[d], s);
    sA[tid] = s; __syncthreads();
    for (int st = 128; st > 0; st >>= 1) {
        if (tid < st) sA[tid] += sA[tid + st];
        __syncthreads();
    }
    if (tid == 0) out[b] = sA[0] * (1.0f / LSEQ) + hb[0];
}

// ---------------------------------------------------------------------------
// kernel_launch
// ---------------------------------------------------------------------------
extern "C" void kernel_launch(void* const* d_in, const int* in_sizes, int n_in,
                              void* d_out, int out_size)
{
    const float* x           = (const float*)d_in[0];
    const float* enc_w       = (const float*)d_in[1];
    const float* enc_b       = (const float*)d_in[2];
    const float* norm_w      = (const float*)d_in[3];
    const float* norm_b      = (const float*)d_in[4];
    const float* attn_norm_w = (const float*)d_in[5];
    const float* attn_norm_b = (const float*)d_in[6];
    const float* ff_norm_w   = (const float*)d_in[7];
    const float* ff_norm_b   = (const float*)d_in[8];
    const float* lam_re      = (const float*)d_in[9];
    const float* lam_im      = (const float*)d_in[10];
    const float* log_step    = (const float*)d_in[11];
    const float* B_re        = (const float*)d_in[12];
    const float* B_im        = (const float*)d_in[13];
    const float* C_re        = (const float*)d_in[14];
    const float* C_im        = (const float*)d_in[15];
    const float* Dvec        = (const float*)d_in[16];
    const float* Wenc        = (const float*)d_in[17];
    const float* Wdec        = (const float*)d_in[18];
    const float* head_w      = (const float*)d_in[19];
    const float* head_b      = (const float*)d_in[20];
    float* out = (float*)d_out;

    float* base = nullptr;
    cudaGetSymbolAddress((void**)&base, g_scratch);

    float* H    = base + OFF_H;
    float* GRE  = base + OFF_GRE;
    float* GIM  = base + OFF_GIM;
    float* Y    = base + OFF_Y;
    float* Z    = base + OFF_Z;
    float* H2   = base + OFF_H2;
    float* POOL = base + OFF_POOL;

    __nv_bfloat16* actb = (__nv_bfloat16*)(base + OFF_ACT);
    const size_t AE = (size_t)MROWS * KP;
    __nv_bfloat16* FXh = actb + 0 * AE;
    __nv_bfloat16* FXl = actb + 1 * AE;
    __nv_bfloat16* XRh = actb + 2 * AE;
    __nv_bfloat16* XRl = actb + 3 * AE;
    __nv_bfloat16* XIh = actb + 4 * AE;
    __nv_bfloat16* XIl = actb + 5 * AE;
    __nv_bfloat16* FYh = actb + 6 * AE;
    __nv_bfloat16* FYl = actb + 7 * AE;
    __nv_bfloat16* Th  = actb + 8 * AE;
    __nv_bfloat16* Tl  = actb + 9 * AE;

    __nv_bfloat16* wb = (__nv_bfloat16*)(base + OFF_WB);
    const size_t W1E = (size_t)NP1 * KP;
    const size_t W2E = (size_t)NP2 * KP;
    const size_t WLE = 10 * W1E + 2 * W2E;

    cudaFuncSetAttribute(gemm_bf16x3, cudaFuncAttributeMaxDynamicSharedMemorySize,
                         GEMM_SMEM_BYTES);

    const int EW_BLOCKS = (int)((MD + 255) / 256);

    enc_kernel<<<EW_BLOCKS, 256>>>(x, enc_w, enc_b, H);

    {
        dim3 gw((unsigned)((W2E + 255) / 256), 6);
        for (int i = 0; i < NLAYERS; i++) {
            convw_layer_kernel<<<gw, 256>>>(
                B_re + (size_t)i*PD*DM, B_im + (size_t)i*PD*DM,
                C_re + (size_t)i*DM*PD, C_im + (size_t)i*DM*PD,
                Wdec + (size_t)i*DM*DM, Wenc + (size_t)i*2*DM*DM,
                wb + (size_t)i * WLE);
        }
    }

    dim3 g9(NP1 / 256, MROWS / 256);    // (5, 64)
    dim3 g17(NP2 / 256, MROWS / 256);   // (9, 64)
    bool padded = false;

    for (int i = 0; i < NLAYERS; i++) {
        const float* nw  = norm_w      + (size_t)i * DM;
        const float* nb  = norm_b      + (size_t)i * DM;
        const float* aw  = attn_norm_w + (size_t)i * DM;
        const float* ab  = attn_norm_b + (size_t)i * DM;
        const float* fw  = ff_norm_w   + (size_t)i * DM;
        const float* fb  = ff_norm_b   + (size_t)i * DM;
        const float* lre = lam_re      + (size_t)i * PD;
        const float* lim = lam_im      + (size_t)i * PD;
        const float* lst = log_step    + (size_t)i * PD;
        const float* dv  = Dvec        + (size_t)i * DM;

        __nv_bfloat16* L = wb + (size_t)i * WLE;
        __nv_bfloat16* Breh = L;             __nv_bfloat16* Brel = L + 1*W1E;
        __nv_bfloat16* Bimh = L + 2*W1E;     __nv_bfloat16* Biml = L + 3*W1E;
        __nv_bfloat16* Creh = L + 4*W1E;     __nv_bfloat16* Crel = L + 5*W1E;
        __nv_bfloat16* Cimh = L + 6*W1E;     __nv_bfloat16* Ciml = L + 7*W1E;
        __nv_bfloat16* Wdh  = L + 8*W1E;     __nv_bfloat16* Wdl  = L + 9*W1E;
        __nv_bfloat16* Weh  = L + 10*W1E;    __nv_bfloat16* Wel  = L + 10*W1E + W2E;

        ln2_kernel<<<MROWS, 256>>>(H, FXh, FXl, nw, nb, aw, ab);

        gemm_bf16x3<<<g9, 256, GEMM_SMEM_BYTES>>>(FXh, FXl, Breh, Brel, GRE, PD, 1.f, 0.f);
        gemm_bf16x3<<<g9, 256, GEMM_SMEM_BYTES>>>(FXh, FXl, Bimh, Biml, GIM, PD, 1.f, 0.f);

        if (!padded) {
            int npad = MROWS * (KP - DM);
            padscan_kernel<<<(npad + 255) / 256, 256>>>(XRh, XRl, XIh, XIl);
            padded = true;
        }

        scan_kernel<<<(BSZ * PD + 127) / 128, 128>>>(GRE, GIM, XRh, XRl, XIh, XIl,
                                                     lre, lim, lst);

        gemm_bf16x3<<<g9, 256, GEMM_SMEM_BYTES>>>(XRh, XRl, Creh, Crel, Y, DM, 1.f, 0.f);
        gemm_bf16x3<<<g9, 256, GEMM_SMEM_BYTES>>>(XIh, XIl, Cimh, Ciml, Y, DM, -1.f, 1.f);

        postln_kernel<<<MROWS, 256>>>(Y, FXh, FXl, dv, fw, fb, FYh, FYl);

        gemm_bf16x3<<<g17, 256, GEMM_SMEM_BYTES>>>(FYh, FYl, Weh, Wel, H2, 2 * DM, 1.f, 0.f);

        {
            size_t n = (size_t)MROWS * KP;
            geglu_kernel<<<(int)((n + 255) / 256), 256>>>(H2, Th, Tl);
        }

        gemm_bf16x3<<<g9, 256, GEMM_SMEM_BYTES>>>(Th, Tl, Wdh, Wdl, Z, DM, 1.f, 0.f);

        addres_kernel<<<EW_BLOCKS, 256>>>(H, Z, FYh, FYl);
    }

    zero_kernel<<<(BSZ * DM + 255) / 256, 256>>>(POOL, BSZ * DM);
    dim3 gp((BSZ * DM + 127) / 128, POOL_CHUNKS);
    pool_kernel<<<gp, 128>>>(H, POOL);
    head_kernel<<<BSZ, 256>>>(POOL, head_w, head_b, out);
}

// round 12
// speedup vs baseline: 1.1879x; 1.1879x over previous
#include <cuda_runtime.h>
#include <cuda_bf16.h>
#include <math.h>
#include <cstdint>

// ---------------------------------------------------------------------------
// Problem constants
// ---------------------------------------------------------------------------
#define BSZ     4
#define LSEQ    4096
#define DM      1048
#define PD      1048
#define NLAYERS 3
#define MROWS   (BSZ*LSEQ)              // 16384
#define MD      ((size_t)MROWS * DM)
#define KP      1088                    // padded K (x1)
#define KP2     2176                    // padded K (concat)
#define GW      2096                    // G width (GRE|GIM)
#define NCH1    17                      // KP/64
#define NCH2    34                      // KP2/64

// float-unit sizes
#define MD_F    17170432ULL             // MROWS*DM
#define G_F     34340864ULL             // MROWS*GW
#define ACT_F   8912896ULL              // MROWS*KP bf16 /2
#define ACT2_F  17825792ULL             // MROWS*KP2 bf16 /2

// weight element counts (bf16, per plane)
#define WB_E    2506752ULL              // 2304*1088
#define WC_E    2506752ULL              // 1152*2176
#define WD_E    1253376ULL              // 1152*1088
#define WE_E    2506752ULL              // 2304*1088
#define WL_BF   (2ULL*(WB_E+WC_E+WD_E+WE_E))   // per-layer bf16
#define WL_F    (WL_BF/2)

#define OFF_H    0ULL
#define OFF_G    (MD_F)
#define OFF_Y    (OFF_G + G_F)
#define OFF_ACT  (OFF_Y + MD_F)
// acts: FXh,FXl (ACT_F each), XCh,XCl (ACT2_F each), FYh,FYl, Th,Tl
#define ACT_TOT  (6ULL*ACT_F + 2ULL*ACT2_F)
#define OFF_WB   (OFF_ACT + ACT_TOT)
#define OFF_POOL (OFF_WB + 3ULL*WL_F)
#define TOT_F    (OFF_POOL + 8192ULL)

__device__ __align__(1024) float g_scratch[TOT_F];

#if defined(__CUDA_ARCH_FEAT_SM103_ALL) || defined(__CUDA_ARCH_SPECIFIC__) || defined(__CUDA_ARCH_FEAT_SM100_ALL)
#define HAS_TCGEN05 1
#else
#define HAS_TCGEN05 0
#endif

__device__ __forceinline__ float gelu_exact(float x) {
    return 0.5f * x * (1.0f + erff(x * 0.70710678118654752f));
}

__device__ __forceinline__ uint32_t smem_u32_of(const void* p) {
    uint32_t a;
    asm("{ .reg .u64 t; cvta.to.shared.u64 t, %1; cvt.u32.u64 %0, t; }"
        : "=r"(a) : "l"(p));
    return a;
}

__device__ __forceinline__ void split_bf16(float v, __nv_bfloat16& h, __nv_bfloat16& l) {
    h = __float2bfloat16(v);
    l = __float2bfloat16(v - __bfloat162float(h));
}

__device__ __forceinline__ uint32_t elect_one_pred() {
    uint32_t pred;
    asm volatile(
        "{\n\t.reg .pred p;\n\telect.sync _|p, 0xFFFFFFFF;\n\t"
        "selp.b32 %0, 1, 0, p;\n\t}" : "=r"(pred));
    return pred;
}

// ---------------------------------------------------------------------------
// Shared PTX macros
// ---------------------------------------------------------------------------
#define CP_ASYNC_16(saddr, gptr) \
    asm volatile("cp.async.cg.shared.global [%0], [%1], 16;" \
        :: "r"(saddr), "l"(gptr) : "memory")
#define CP_ASYNC_MBAR_ARRIVE_NOINC(mbar) \
    asm volatile("cp.async.mbarrier.arrive.noinc.shared::cta.b64 [%0];" \
        :: "r"((uint32_t)(mbar)) : "memory")

#define MBARRIER_INIT(mbar, count) \
    asm volatile("mbarrier.init.shared.b64 [%0], %1;" \
        :: "r"((uint32_t)(mbar)), "r"((uint32_t)(count)) : "memory")
#define MBARRIER_WAIT_PARITY(mbar, parity) do { \
    uint32_t _mbar = (uint32_t)(mbar); \
    uint32_t _parity = (uint32_t)(parity); \
    uint32_t _done; \
    asm volatile( \
        "{\n\t.reg .pred p;\n\t" \
        "mbarrier.try_wait.parity.acquire.cta.shared::cta.b64 p, [%1], %2;\n\t" \
        "selp.b32 %0, 1, 0, p;\n\t}" \
        : "=r"(_done) : "r"(_mbar), "r"(_parity) : "memory"); \
    if (!_done) { \
        asm volatile( \
            "{\n\t.reg .pred P1;\n\t" \
            "WAIT_LOOP_%=:\n\t" \
            "mbarrier.try_wait.parity.acquire.cta.shared::cta.b64 P1, [%0], %1, 0x989680;\n\t" \
            "@P1 bra.uni WAIT_DONE_%=;\n\t" \
            "bra.uni WAIT_LOOP_%=;\n\t" \
            "WAIT_DONE_%=:\n\t}" \
            :: "r"(_mbar), "r"(_parity) : "memory"); \
    } \
} while(0)

#define TPLANE 16384
#define TSTAGE 65536
#define GEMM_SMEM_BYTES (1024 + 3*TSTAGE)   // 197632

// emode: 0 = C[m,N] = alpha*acc + beta*C
//        1 = GEGLU: cols pair (a,g) -> Oh/Ol bf16 at d=(n)/2, d<KP
//        2 = residual: C(=H)[m,DM] += acc + (FYh+FYl), n<DM
#if HAS_TCGEN05
// ===== tcgen05 path ==========================================================
#define TCGEN05_ALLOC(saddr, nCols) \
    asm volatile("tcgen05.alloc.cta_group::1.sync.aligned.shared::cta.b32 [%0], %1;" \
        :: "r"((uint32_t)(saddr)), "r"((uint32_t)(nCols)) : "memory")
#define TCGEN05_DEALLOC(tmem, nCols) \
    asm volatile("tcgen05.dealloc.cta_group::1.sync.aligned.b32 %0, %1;" \
        :: "r"(tmem), "r"((uint32_t)(nCols)))
#define TCGEN05_RELINQUISH() \
    asm volatile("tcgen05.relinquish_alloc_permit.cta_group::1.sync.aligned;")
#define TCGEN05_COMMIT(mbar) \
    asm volatile("tcgen05.commit.cta_group::1.mbarrier::arrive::one.shared::cluster.b64 [%0];" \
        :: "r"((uint32_t)(mbar)) : "memory")
#define TCGEN05_FENCE_AFTER() \
    asm volatile("tcgen05.fence::after_thread_sync;" ::: "memory")
#define TCGEN05_WAIT_LD() \
    asm volatile("tcgen05.wait::ld.sync.aligned;" ::: "memory")
#define FENCE_PROXY_ASYNC() \
    asm volatile("fence.proxy.async.shared::cta;" ::: "memory")
#define TCGEN05_LD_32X32B_X32(r, taddr) \
    asm volatile( \
        "tcgen05.ld.sync.aligned.32x32b.x32.b32 " \
        "{%0, %1, %2, %3, %4, %5, %6, %7, " \
        " %8, %9, %10, %11, %12, %13, %14, %15, " \
        " %16, %17, %18, %19, %20, %21, %22, %23, " \
        " %24, %25, %26, %27, %28, %29, %30, %31}, [%32];" \
        : "=r"((r)[0]),  "=r"((r)[1]),  "=r"((r)[2]),  "=r"((r)[3]), \
          "=r"((r)[4]),  "=r"((r)[5]),  "=r"((r)[6]),  "=r"((r)[7]), \
          "=r"((r)[8]),  "=r"((r)[9]),  "=r"((r)[10]), "=r"((r)[11]), \
          "=r"((r)[12]), "=r"((r)[13]), "=r"((r)[14]), "=r"((r)[15]), \
          "=r"((r)[16]), "=r"((r)[17]), "=r"((r)[18]), "=r"((r)[19]), \
          "=r"((r)[20]), "=r"((r)[21]), "=r"((r)[22]), "=r"((r)[23]), \
          "=r"((r)[24]), "=r"((r)[25]), "=r"((r)[26]), "=r"((r)[27]), \
          "=r"((r)[28]), "=r"((r)[29]), "=r"((r)[30]), "=r"((r)[31]) \
        : "r"(taddr))

static constexpr uint64_t SMEM_DESC_BASE_SW128 =
    (uint64_t(2) << 61) | (uint64_t(1) << 46) | (uint64_t(64) << 32) | (uint64_t(1) << 16);
#define MAKE_SMEM_DESC(base_addr) \
    (SMEM_DESC_BASE_SW128 | ((uint64_t)((base_addr) >> 4) & 0x3FFF))

static constexpr uint32_t GIDESC =
    (1u<<4) | (1u<<7) | (1u<<10) | ((128u/8u)<<17) | ((128u/16u)<<24);

__device__ __forceinline__ void mma_f16_ss(uint32_t d_tmem, uint64_t a_desc,
                                           uint64_t b_desc, uint32_t en) {
    asm volatile(
        "{\n\t.reg .pred p;\n\tsetp.ne.u32 p, %4, 0;\n\t"
        "tcgen05.mma.cta_group::1.kind::f16 [%0], %1, %2, %3, {%5, %5, %5, %5}, p;\n\t}"
        :: "r"(d_tmem), "l"(a_desc), "l"(b_desc), "r"(GIDESC), "r"(en), "r"(0u)
        : "memory");
}

// smem: [0] tmem ptr, [16..40) full[3], [40..64) done[3], data at 1024
__global__ __launch_bounds__(256) void gemm_bf16x3(
    const __nv_bfloat16* __restrict__ Ah, const __nv_bfloat16* __restrict__ Al,
    const __nv_bfloat16* __restrict__ Bh, const __nv_bfloat16* __restrict__ Bl,
    float* __restrict__ C, int N, float alpha, float beta,
    int kchunks, int rowstride, int emode,
    __nv_bfloat16* __restrict__ Oh, __nv_bfloat16* __restrict__ Ol,
    const __nv_bfloat16* __restrict__ FYh, const __nv_bfloat16* __restrict__ FYl)
{
    extern __shared__ __align__(1024) char smem[];
    const uint32_t sbase = smem_u32_of(smem);
    const int tid = threadIdx.x;
    const int wid = tid >> 5;
    const int lid = tid & 31;

    if (wid == 0) {
        TCGEN05_ALLOC(sbase + 0, 128);
        TCGEN05_RELINQUISH();
    }
    if (tid == 0) {
        #pragma unroll
        for (int s = 0; s < 3; s++) {
            MBARRIER_INIT(sbase + 16 + 8 * s, 256);
            MBARRIER_INIT(sbase + 40 + 8 * s, 1);
        }
    }
    __syncthreads();
    uint32_t tmem;
    asm volatile("ld.shared.b32 %0, [%1];" : "=r"(tmem) : "r"(sbase));

    const __nv_bfloat16* srcs[4];
    srcs[0] = Ah + (size_t)blockIdx.y * 128 * rowstride;
    srcs[1] = Al + (size_t)blockIdx.y * 128 * rowstride;
    srcs[2] = Bh + (size_t)blockIdx.x * 128 * rowstride;
    srcs[3] = Bl + (size_t)blockIdx.x * 128 * rowstride;

    auto prefetch = [&](int kc) {
        const int s = kc % 3;
        const int k0 = kc * 64;
        const uint32_t stb = sbase + 1024 + s * TSTAGE;
        #pragma unroll
        for (int i = 0; i < 16; i++) {
            int c  = i * 256 + tid;
            int pl = c >> 10;
            int r  = (c >> 3) & 127;
            int j  = c & 7;
            uint32_t dst = stb + pl * TPLANE + r * 128 + ((j ^ (r & 7)) << 4);
            CP_ASYNC_16(dst, srcs[pl] + (size_t)r * rowstride + k0 + j * 8);
        }
        CP_ASYNC_MBAR_ARRIVE_NOINC(sbase + 16 + 8 * s);
    };

    const uint32_t ismma = (wid == 0) ? elect_one_pred() : 0u;

    prefetch(0);
    prefetch(1);
    prefetch(2);

    for (int kc = 0; kc < kchunks; kc++) {
        const int s = kc % 3;
        const uint32_t ph = (kc / 3) & 1;

        if (ismma) {
            MBARRIER_WAIT_PARITY(sbase + 16 + 8 * s, ph);
            FENCE_PROXY_ASYNC();
            const uint32_t stb = sbase + 1024 + s * TSTAGE;
            uint64_t dAh = MAKE_SMEM_DESC(stb);
            uint64_t dAl = MAKE_SMEM_DESC(stb + TPLANE);
            uint64_t dBh = MAKE_SMEM_DESC(stb + 2 * TPLANE);
            uint64_t dBl = MAKE_SMEM_DESC(stb + 3 * TPLANE);
            #pragma unroll
            for (int ks = 0; ks < 4; ks++) {
                mma_f16_ss(tmem, dAh + ks * 2, dBh + ks * 2, (kc != 0) || (ks != 0));
                mma_f16_ss(tmem, dAh + ks * 2, dBl + ks * 2, 1u);
                mma_f16_ss(tmem, dAl + ks * 2, dBh + ks * 2, 1u);
            }
            TCGEN05_COMMIT(sbase + 40 + 8 * s);
        }

        if (kc + 3 < kchunks) {
            MBARRIER_WAIT_PARITY(sbase + 40 + 8 * s, ph);
            prefetch(kc + 3);
        }
    }

    if (ismma) {
        int pc = kchunks - 1;
        MBARRIER_WAIT_PARITY(sbase + 40 + 8 * (pc % 3), (pc / 3) & 1);
    }
    __syncthreads();
    TCGEN05_FENCE_AFTER();

    if (wid < 4) {
        const int nbase = blockIdx.x * 128;
        const size_t m = (size_t)blockIdx.y * 128 + wid * 32 + lid;
        for (int cb = 0; cb < 4; cb++) {
            uint32_t r[32];
            TCGEN05_LD_32X32B_X32(r, tmem + cb * 32);
            TCGEN05_WAIT_LD();
            if (emode == 0) {
                float* crow = C + m * (size_t)N;
                #pragma unroll
                for (int c = 0; c < 32; c += 4) {
                    int n = nbase + cb * 32 + c;
                    if (n + 3 < N) {
                        float4 v;
                        v.x = alpha * __uint_as_float(r[c + 0]);
                        v.y = alpha * __uint_as_float(r[c + 1]);
                        v.z = alpha * __uint_as_float(r[c + 2]);
                        v.w = alpha * __uint_as_float(r[c + 3]);
                        if (beta != 0.f) {
                            float4 o = *reinterpret_cast<const float4*>(crow + n);
                            v.x = fmaf(beta, o.x, v.x);
                            v.y = fmaf(beta, o.y, v.y);
                            v.z = fmaf(beta, o.z, v.z);
                            v.w = fmaf(beta, o.w, v.w);
                        }
                        *reinterpret_cast<float4*>(crow + n) = v;
                    } else {
                        for (int q = 0; q < 4; q++) {
                            int nn = n + q;
                            if (nn < N) {
                                float v = alpha * __uint_as_float(r[c + q]);
                                if (beta != 0.f) v = fmaf(beta, crow[nn], v);
                                crow[nn] = v;
                            }
                        }
                    }
                }
            } else if (emode == 1) {
                // GEGLU pairs: even col = a, odd col = g
                int dbase = (nbase + cb * 32) >> 1;
                #pragma unroll
                for (int u = 0; u < 16; u++) {
                    int d = dbase + u;
                    if (d < KP) {
                        float a = __uint_as_float(r[2 * u]);
                        float g = __uint_as_float(r[2 * u + 1]);
                        float val = a * gelu_exact(g);
                        __nv_bfloat16 h, l; split_bf16(val, h, l);
                        Oh[m * KP + d] = h;
                        Ol[m * KP + d] = l;
                    }
                }
            } else {
                // residual: H[m,DM] += acc + fy
                float* hrow = C + m * (size_t)DM;
                #pragma unroll
                for (int c = 0; c < 32; c++) {
                    int n = nbase + cb * 32 + c;
                    if (n < DM) {
                        size_t j = m * (size_t)KP + n;
                        float fy = __bfloat162float(FYh[j]) + __bfloat162float(FYl[j]);
                        hrow[n] += __uint_as_float(r[c]) + fy;
                    }
                }
            }
        }
    }
    __syncthreads();
    if (wid == 0) TCGEN05_DEALLOC(tmem, 128);
}

#else
// ===== naive fallback (generic pass; never runs on sm_103a hardware) ========
__global__ __launch_bounds__(256) void gemm_bf16x3(
    const __nv_bfloat16* __restrict__ Ah, const __nv_bfloat16* __restrict__ Al,
    const __nv_bfloat16* __restrict__ Bh, const __nv_bfloat16* __restrict__ Bl,
    float* __restrict__ C, int N, float alpha, float beta,
    int kchunks, int rowstride, int emode,
    __nv_bfloat16* __restrict__ Oh, __nv_bfloat16* __restrict__ Ol,
    const __nv_bfloat16* __restrict__ FYh, const __nv_bfloat16* __restrict__ FYl)
{
    const int tid = threadIdx.x;
    if (tid >= 128) return;
    const size_t m = (size_t)blockIdx.y * 128 + tid;
    const int n0 = blockIdx.x * 128;
    const int K = kchunks * 64;
    const __nv_bfloat16* arh = Ah + m * rowstride;
    const __nv_bfloat16* arl = Al + m * rowstride;

    auto dot = [&](int n) {
        const __nv_bfloat16* brh = Bh + (size_t)n * rowstride;
        const __nv_bfloat16* brl = Bl + (size_t)n * rowstride;
        float acc = 0.f;
        for (int k = 0; k < K; k++) {
            float ahv = __bfloat162float(arh[k]);
            float alv = __bfloat162float(arl[k]);
            float bhv = __bfloat162float(brh[k]);
            float blv = __bfloat162float(brl[k]);
            acc = fmaf(ahv, bhv, acc);
            acc = fmaf(ahv, blv, acc);
            acc = fmaf(alv, bhv, acc);
        }
        return acc;
    };

    if (emode == 0) {
        for (int j = 0; j < 128; j++) {
            int n = n0 + j;
            if (n >= N) break;
            size_t idx = m * (size_t)N + n;
            float v = alpha * dot(n);
            if (beta != 0.f) v = fmaf(beta, C[idx], v);
            C[idx] = v;
        }
    } else if (emode == 1) {
        for (int j = 0; j < 128; j += 2) {
            int d = (n0 + j) >> 1;
            if (d >= KP) break;
            float a = dot(n0 + j);
            float g = dot(n0 + j + 1);
            float val = a * gelu_exact(g);
            __nv_bfloat16 h, l; split_bf16(val, h, l);
            Oh[m * KP + d] = h;
            Ol[m * KP + d] = l;
        }
    } else {
        for (int j = 0; j < 128; j++) {
            int n = n0 + j;
            if (n >= DM) break;
            size_t jj = m * (size_t)KP + n;
            float fy = __bfloat162float(FYh[jj]) + __bfloat162float(FYl[jj]);
            C[m * (size_t)DM + n] += dot(n) + fy;
        }
    }
}
#endif

// ---------------------------------------------------------------------------
// Elementwise / row kernels
// ---------------------------------------------------------------------------
__global__ void enc_kernel(const float* __restrict__ x,
                           const float* __restrict__ ew,
                           const float* __restrict__ eb,
                           float* __restrict__ H)
{
    size_t i = (size_t)blockIdx.x * blockDim.x + threadIdx.x;
    if (i >= MD) return;
    int d = (int)(i % DM);
    int m = (int)(i / DM);
    H[i] = fmaf(x[m], ew[d], eb[d]);
}

__global__ __launch_bounds__(256) void ln2_kernel(
    const float* __restrict__ X,
    __nv_bfloat16* __restrict__ Oh, __nv_bfloat16* __restrict__ Ol,
    const float* __restrict__ w1, const float* __restrict__ b1,
    const float* __restrict__ w2, const float* __restrict__ b2)
{
    const int row = blockIdx.x;
    const int tid = threadIdx.x;
    const float* x = X + (size_t)row * DM;
    const size_t ro = (size_t)row * KP;
    __shared__ float sA[256], sB[256];

    float v[5];
    float s = 0.f, ss = 0.f;
    #pragma unroll
    for (int k = 0; k < 5; k++) {
        int d = tid + k * 256;
        float t = (d < DM) ? x[d] : 0.f;
        v[k] = t; s += t; ss += t * t;
    }
    sA[tid] = s; sB[tid] = ss; __syncthreads();
    for (int st = 128; st > 0; st >>= 1) {
        if (tid < st) { sA[tid] += sA[tid + st]; sB[tid] += sB[tid + st]; }
        __syncthreads();
    }
    float mu  = sA[0] * (1.0f / DM);
    float var = sB[0] * (1.0f / DM) - mu * mu;
    float rs  = rsqrtf(var + 1e-5f);
    __syncthreads();

    s = 0.f; ss = 0.f;
    #pragma unroll
    for (int k = 0; k < 5; k++) {
        int d = tid + k * 256;
        float r = 0.f;
        if (d < DM) r = fmaf((v[k] - mu) * rs, w1[d], b1[d]);
        v[k] = r; s += r; ss += r * r;
    }
    sA[tid] = s; sB[tid] = ss; __syncthreads();
    for (int st = 128; st > 0; st >>= 1) {
        if (tid < st) { sA[tid] += sA[tid + st]; sB[tid] += sB[tid + st]; }
        __syncthreads();
    }
    float mu2  = sA[0] * (1.0f / DM);
    float var2 = sB[0] * (1.0f / DM) - mu2 * mu2;
    float rs2  = rsqrtf(var2 + 1e-5f);
    #pragma unroll
    for (int k = 0; k < 5; k++) {
        int d = tid + k * 256;
        if (d < DM) {
            float r2 = fmaf((v[k] - mu2) * rs2, w2[d], b2[d]);
            __nv_bfloat16 h, l; split_bf16(r2, h, l);
            Oh[ro + d] = h; Ol[ro + d] = l;
        } else if (d < KP) {
            Oh[ro + d] = __float2bfloat16(0.f);
            Ol[ro + d] = __float2bfloat16(0.f);
        }
    }
}

__global__ __launch_bounds__(256) void postln_kernel(
    const float* __restrict__ Y,
    const __nv_bfloat16* __restrict__ FXh, const __nv_bfloat16* __restrict__ FXl,
    const float* __restrict__ dv,
    const float* __restrict__ w, const float* __restrict__ b,
    __nv_bfloat16* __restrict__ Oh, __nv_bfloat16* __restrict__ Ol)
{
    const int row = blockIdx.x;
    const int tid = threadIdx.x;
    const float* y = Y + (size_t)row * DM;
    const size_t ro = (size_t)row * KP;
    __shared__ float sA[256], sB[256];

    float v[5];
    float s = 0.f, ss = 0.f;
    #pragma unroll
    for (int k = 0; k < 5; k++) {
        int d = tid + k * 256;
        float z = 0.f;
        if (d < DM) {
            float f = __bfloat162float(FXh[ro + d]) + __bfloat162float(FXl[ro + d]);
            float e = fmaf(dv[d], f, y[d]);
            z = gelu_exact(e) + f;
        }
        v[k] = z; s += z; ss += z * z;
    }
    sA[tid] = s; sB[tid] = ss; __syncthreads();
    for (int st = 128; st > 0; st >>= 1) {
        if (tid < st) { sA[tid] += sA[tid + st]; sB[tid] += sB[tid + st]; }
        __syncthreads();
    }
    float mu  = sA[0] * (1.0f / DM);
    float var = sB[0] * (1.0f / DM) - mu * mu;
    float rs  = rsqrtf(var + 1e-5f);
    #pragma unroll
    for (int k = 0; k < 5; k++) {
        int d = tid + k * 256;
        if (d < DM) {
            float r = fmaf((v[k] - mu) * rs, w[d], b[d]);
            __nv_bfloat16 h, l; split_bf16(r, h, l);
            Oh[ro + d] = h; Ol[ro + d] = l;
        } else if (d < KP) {
            Oh[ro + d] = __float2bfloat16(0.f);
            Ol[ro + d] = __float2bfloat16(0.f);
        }
    }
}

// scan: reads G[row, 2096] (re at col p, im at col PD+p),
// writes XC planes [row, KP2): XR at col p, XI at col KP+p
__global__ void scan_kernel(
    const float* __restrict__ G,
    __nv_bfloat16* __restrict__ XCh, __nv_bfloat16* __restrict__ XCl,
    const float* __restrict__ lr_, const float* __restrict__ li_,
    const float* __restrict__ ls_)
{
    int t = blockIdx.x * blockDim.x + threadIdx.x;
    if (t >= BSZ * PD) return;
    int b = t / PD, p = t % PD;

    float lr = lr_[p], li = li_[p];
    float st = expf(ls_[p]);
    float er = expf(lr * st);
    float sn, cs; sincosf(li * st, &sn, &cs);
    float ar = er * cs, ai = er * sn;
    float inv = 1.0f / (lr * lr + li * li);
    float nr = ar - 1.0f;
    float cr = (nr * lr + ai * li) * inv;
    float ci = (ai * lr - nr * li) * inv;

    size_t goff = (size_t)b * LSEQ * GW;
    const float* gr = G + goff + p;
    const float* gi = G + goff + PD + p;
    size_t ooff = (size_t)b * LSEQ * KP2;

    float xr = 0.f, xi = 0.f;
    #pragma unroll 4
    for (int l = 0; l < LSEQ; l++) {
        float ur = gr[(size_t)l * GW];
        float ui = gi[(size_t)l * GW];
        float br = fmaf(cr, ur, -ci * ui);
        float bi = fmaf(cr, ui,  ci * ur);
        float nxr = fmaf(ar, xr, fmaf(-ai, xi, br));
        float nxi = fmaf(ar, xi, fmaf( ai, xr, bi));
        xr = nxr; xi = nxi;
        size_t o = ooff + (size_t)l * KP2;
        __nv_bfloat16 h, lo;
        split_bf16(xr, h, lo); XCh[o + p] = h;      XCl[o + p] = lo;
        split_bf16(xi, h, lo); XCh[o + KP + p] = h; XCl[o + KP + p] = lo;
    }
}

// zero pad cols [DM,KP) and [KP+DM,KP2) of the XC planes (once per launch)
__global__ void padscan_kernel(__nv_bfloat16* p0, __nv_bfloat16* p1)
{
    int i = blockIdx.x * blockDim.x + threadIdx.x;
    const int PADW = 2 * (KP - DM);   // 80
    if (i >= MROWS * PADW) return;
    int r = i / PADW, q = i % PADW;
    int c = (q < (KP - DM)) ? (DM + q) : (KP + DM + q - (KP - DM));
    size_t idx = (size_t)r * KP2 + c;
    __nv_bfloat16 z = __float2bfloat16(0.f);
    p0[idx] = z; p1[idx] = z;
}

// Per-layer weight conversion: 4 fused weight groups
// w=0: Bcomb [2304, KP]: rows 0..1047=Bre, 1048..2095=Bim
// w=1: CC    [1152, KP2]: k<1048: Cre; 1088<=k<2136: -Cim
// w=2: Wd    [1152, KP]
// w=3: We2   [2304, KP]: row 2d = Wenc[d], row 2d+1 = Wenc[DM+d]
__global__ void convw_layer_kernel(
    const float* __restrict__ Bre, const float* __restrict__ Bim,
    const float* __restrict__ Cre, const float* __restrict__ Cim,
    const float* __restrict__ Wd,  const float* __restrict__ We,
    __nv_bfloat16* __restrict__ L)
{
    int w = blockIdx.y;
    size_t i = (size_t)blockIdx.x * blockDim.x + threadIdx.x;
    float v = 0.f;
    __nv_bfloat16 *Wh, *Wl;
    if (w == 0) {
        if (i >= WB_E) return;
        Wh = L; Wl = L + WB_E;
        int n = (int)(i / KP), k = (int)(i % KP);
        if (k < DM) {
            if (n < DM)            v = Bre[(size_t)n * DM + k];
            else if (n < 2 * DM)   v = Bim[(size_t)(n - DM) * DM + k];
        }
    } else if (w == 1) {
        if (i >= WC_E) return;
        Wh = L + 2 * WB_E; Wl = Wh + WC_E;
        int n = (int)(i / KP2), k = (int)(i % KP2);
        if (n < DM) {
            if (k < DM)                      v = Cre[(size_t)n * PD + k];
            else if (k >= KP && k < KP + DM) v = -Cim[(size_t)n * PD + (k - KP)];
        }
    } else if (w == 2) {
        if (i >= WD_E) return;
        Wh = L + 2 * WB_E + 2 * WC_E; Wl = Wh + WD_E;
        int n = (int)(i / KP), k = (int)(i % KP);
        if (n < DM && k < DM) v = Wd[(size_t)n * DM + k];
    } else {
        if (i >= WE_E) return;
        Wh = L + 2 * WB_E + 2 * WC_E + 2 * WD_E; Wl = Wh + WE_E;
        int n = (int)(i / KP), k = (int)(i % KP);
        if (n < 2 * DM && k < DM) {
            int d = n >> 1;
            int srcrow = (n & 1) ? (DM + d) : d;
            v = We[(size_t)srcrow * DM + k];
        }
    }
    __nv_bfloat16 h, l; split_bf16(v, h, l);
    Wh[i] = h; Wl[i] = l;
}

__global__ void zero_kernel(float* __restrict__ P, int n)
{
    int i = blockIdx.x * blockDim.x + threadIdx.x;
    if (i < n) P[i] = 0.f;
}

#define POOL_CHUNKS 32
__global__ void pool_kernel(const float* __restrict__ H, float* __restrict__ POOL)
{
    int t = blockIdx.x * blockDim.x + threadIdx.x;
    if (t >= BSZ * DM) return;
    int b = t / DM, d = t % DM;
    const int CL = LSEQ / POOL_CHUNKS;
    int l0 = blockIdx.y * CL;
    const float* h = H + (size_t)b * LSEQ * DM + (size_t)l0 * DM + d;
    float s = 0.f;
    #pragma unroll 8
    for (int l = 0; l < CL; l++) s += h[(size_t)l * DM];
    atomicAdd(&POOL[t], s);
}

__global__ void head_kernel(const float* __restrict__ POOL,
                            const float* __restrict__ hw,
                            const float* __restrict__ hb,
                            float* __restrict__ out)
{
    int b = blockIdx.x;
    int tid = threadIdx.x;
    __shared__ float sA[256];
    float s = 0.f;
    for (int d = tid; d < DM; d += 256) s = fmaf(POOL[b * DM + d], hw[d], s);
    sA[tid] = s; __syncthreads();
    for (int st = 128; st > 0; st >>= 1) {
        if (tid < st) sA[tid] += sA[tid + st];
        __syncthreads();
    }
    if (tid == 0) out[b] = sA[0] * (1.0f / LSEQ) + hb[0];
}

// ---------------------------------------------------------------------------
// kernel_launch
// ---------------------------------------------------------------------------
extern "C" void kernel_launch(void* const* d_in, const int* in_sizes, int n_in,
                              void* d_out, int out_size)
{
    const float* x           = (const float*)d_in[0];
    const float* enc_w       = (const float*)d_in[1];
    const float* enc_b       = (const float*)d_in[2];
    const float* norm_w      = (const float*)d_in[3];
    const float* norm_b      = (const float*)d_in[4];
    const float* attn_norm_w = (const float*)d_in[5];
    const float* attn_norm_b = (const float*)d_in[6];
    const float* ff_norm_w   = (const float*)d_in[7];
    const float* ff_norm_b   = (const float*)d_in[8];
    const float* lam_re      = (const float*)d_in[9];
    const float* lam_im      = (const float*)d_in[10];
    const float* log_step    = (const float*)d_in[11];
    const float* B_re        = (const float*)d_in[12];
    const float* B_im        = (const float*)d_in[13];
    const float* C_re        = (const float*)d_in[14];
    const float* C_im        = (const float*)d_in[15];
    const float* Dvec        = (const float*)d_in[16];
    const float* Wenc        = (const float*)d_in[17];
    const float* Wdec        = (const float*)d_in[18];
    const float* head_w      = (const float*)d_in[19];
    const float* head_b      = (const float*)d_in[20];
    float* out = (float*)d_out;

    float* base = nullptr;
    cudaGetSymbolAddress((void**)&base, g_scratch);

    float* H    = base + OFF_H;
    float* G    = base + OFF_G;
    float* Y    = base + OFF_Y;
    float* POOL = base + OFF_POOL;

    __nv_bfloat16* actb = (__nv_bfloat16*)(base + OFF_ACT);
    const size_t AE  = (size_t)MROWS * KP;
    const size_t AE2 = (size_t)MROWS * KP2;
    __nv_bfloat16* FXh = actb;
    __nv_bfloat16* FXl = FXh + AE;
    __nv_bfloat16* XCh = FXl + AE;
    __nv_bfloat16* XCl = XCh + AE2;
    __nv_bfloat16* FYh = XCl + AE2;
    __nv_bfloat16* FYl = FYh + AE;
    __nv_bfloat16* Th  = FYl + AE;
    __nv_bfloat16* Tl  = Th + AE;

    __nv_bfloat16* wb = (__nv_bfloat16*)(base + OFF_WB);

    cudaFuncSetAttribute(gemm_bf16x3, cudaFuncAttributeMaxDynamicSharedMemorySize,
                         GEMM_SMEM_BYTES);

    const int EW_BLOCKS = (int)((MD + 255) / 256);

    enc_kernel<<<EW_BLOCKS, 256>>>(x, enc_w, enc_b, H);

    {
        dim3 gw((unsigned)((WB_E + 255) / 256), 4);   // WB_E == WC_E == WE_E (max)
        for (int i = 0; i < NLAYERS; i++) {
            convw_layer_kernel<<<gw, 256>>>(
                B_re + (size_t)i*PD*DM, B_im + (size_t)i*PD*DM,
                C_re + (size_t)i*DM*PD, C_im + (size_t)i*DM*PD,
                Wdec + (size_t)i*DM*DM, Wenc + (size_t)i*2*DM*DM,
                wb + (size_t)i * WL_BF);
        }
    }

    dim3 gB(2304 / 128, MROWS / 128);   // (18,128) B-proj & Wenc
    dim3 gC(1152 / 128, MROWS / 128);   // (9,128)  C-proj & Wdec
    bool padded = false;

    for (int i = 0; i < NLAYERS; i++) {
        const float* nw  = norm_w      + (size_t)i * DM;
        const float* nb  = norm_b      + (size_t)i * DM;
        const float* aw  = attn_norm_w + (size_t)i * DM;
        const float* ab  = attn_norm_b + (size_t)i * DM;
        const float* fw  = ff_norm_w   + (size_t)i * DM;
        const float* fb  = ff_norm_b   + (size_t)i * DM;
        const float* lre = lam_re      + (size_t)i * PD;
        const float* lim = lam_im      + (size_t)i * PD;
        const float* lst = log_step    + (size_t)i * PD;
        const float* dv  = Dvec        + (size_t)i * DM;

        __nv_bfloat16* L = wb + (size_t)i * WL_BF;
        __nv_bfloat16* Bch = L;
        __nv_bfloat16* Bcl = L + WB_E;
        __nv_bfloat16* CCh = L + 2*WB_E;
        __nv_bfloat16* CCl = CCh + WC_E;
        __nv_bfloat16* Wdh = L + 2*WB_E + 2*WC_E;
        __nv_bfloat16* Wdl = Wdh + WD_E;
        __nv_bfloat16* Weh = L + 2*WB_E + 2*WC_E + 2*WD_E;
        __nv_bfloat16* Wel = Weh + WE_E;

        ln2_kernel<<<MROWS, 256>>>(H, FXh, FXl, nw, nb, aw, ab);

        // G[.,2096] = FX @ [Bre;Bim]^T
        gemm_bf16x3<<<gB, 256, GEMM_SMEM_BYTES>>>(
            FXh, FXl, Bch, Bcl, G, GW, 1.f, 0.f, NCH1, KP, 0,
            nullptr, nullptr, nullptr, nullptr);

        if (!padded) {
            int npad = MROWS * 2 * (KP - DM);
            padscan_kernel<<<(npad + 255) / 256, 256>>>(XCh, XCl);
            padded = true;
        }

        scan_kernel<<<(BSZ * PD + 127) / 128, 128>>>(G, XCh, XCl, lre, lim, lst);

        // Y = [XR|XI] @ [Cre|-Cim]^T  (K = 2176)
        gemm_bf16x3<<<gC, 256, GEMM_SMEM_BYTES>>>(
            XCh, XCl, CCh, CCl, Y, DM, 1.f, 0.f, NCH2, KP2, 0,
            nullptr, nullptr, nullptr, nullptr);

        postln_kernel<<<MROWS, 256>>>(Y, FXh, FXl, dv, fw, fb, FYh, FYl);

        // T = GEGLU(FY @ We2^T)  fused epilogue -> Th/Tl
        gemm_bf16x3<<<gB, 256, GEMM_SMEM_BYTES>>>(
            FYh, FYl, Weh, Wel, nullptr, 2304, 1.f, 0.f, NCH1, KP, 1,
            Th, Tl, nullptr, nullptr);

        // H += T @ Wd^T + FY   fused epilogue
        gemm_bf16x3<<<gC, 256, GEMM_SMEM_BYTES>>>(
            Th, Tl, Wdh, Wdl, H, DM, 1.f, 0.f, NCH1, KP, 2,
            nullptr, nullptr, FYh, FYl);
    }

    zero_kernel<<<(BSZ * DM + 255) / 256, 256>>>(POOL, BSZ * DM);
    dim3 gp((BSZ * DM + 127) / 128, POOL_CHUNKS);
    pool_kernel<<<gp, 128>>>(H, POOL);
    head_kernel<<<BSZ, 256>>>(POOL, head_w, head_b, out);
}